// round 1
// baseline (speedup 1.0000x reference)
#include <cuda_runtime.h>
#include <cstdint>
#include <cstddef>

#define E_TOTAL 400000
#define DIM 128
#define G_TOTAL 512
#define BM 128
#define SSTR 132          // 128 + 4 padding: conflict-free MMA operand LDS
#define NTHREADS 256
#define SMEM_BYTES (2 * BM * SSTR * 4)

// Scratch (static device arrays are allowed; allocation is not)
__device__ float g_UB[G_TOTAL * DIM];     // u @ W1[384:512] + b1, exact fp32
__device__ int   g_batch[E_TOTAL];        // normalized batch indices

__device__ __forceinline__ float to_tf32(float x) {
    unsigned r;
    asm("cvt.rna.tf32.f32 %0, %1;" : "=r"(r) : "f"(x));
    return __uint_as_float(r);
}

__device__ __forceinline__ void mma_tf32(float* c, const unsigned* a, unsigned b0, unsigned b1) {
    asm volatile(
        "mma.sync.aligned.m16n8k8.row.col.f32.tf32.tf32.f32 "
        "{%0,%1,%2,%3},{%4,%5,%6,%7},{%8,%9},{%0,%1,%2,%3};\n"
        : "+f"(c[0]), "+f"(c[1]), "+f"(c[2]), "+f"(c[3])
        : "r"(a[0]), "r"(a[1]), "r"(a[2]), "r"(a[3]), "r"(b0), "r"(b1));
}

// ---------------------------------------------------------------------------
// batch may arrive as int32 (JAX x64 disabled) or int64. Detect: batch is
// sorted ascending over 400k draws from [0,512); if stored as int64 the odd
// 32-bit word at index E-1 is a high half == 0; if int32 it is the last
// (largest) element, which is nonzero with overwhelming certainty.
// ---------------------------------------------------------------------------
__global__ void batch_norm_kernel(const int* __restrict__ bp32) {
    bool is64 = (bp32[E_TOTAL - 1] == 0);
    int i = blockIdx.x * blockDim.x + threadIdx.x;
    if (i < E_TOTAL) {
        g_batch[i] = is64 ? (int)(((const long long*)bp32)[i]) : bp32[i];
    }
}

// UB[g][n] = b1[n] + sum_k u[g][k] * W1[384+k][n]   (exact fp32, tiny)
__global__ void ub_kernel(const float* __restrict__ u, const float* __restrict__ W1,
                          const float* __restrict__ b1) {
    __shared__ float us[DIM];
    int gi = blockIdx.x, n = threadIdx.x;
    us[n] = u[gi * DIM + n];
    __syncthreads();
    float acc = b1[n];
    const float* w = W1 + 3 * DIM * DIM + n;
#pragma unroll 8
    for (int k = 0; k < DIM; ++k) acc += us[k] * w[k * DIM];
    g_UB[gi * DIM + n] = acc;
}

// 16 k-steps of m16n8k8 over a 128-deep K chunk.
// sA: [row][k] stride SSTR (A operand), sB: [n][k] stride SSTR (B operand).
__device__ __forceinline__ void mma_block(const float* __restrict__ sA,
                                          const float* __restrict__ sB,
                                          float acc[2][8][4],
                                          int wm, int wn, int g, int tg) {
#pragma unroll
    for (int ks = 0; ks < 16; ++ks) {
        const int k0 = ks * 8;
        unsigned a[2][4];
#pragma unroll
        for (int mi = 0; mi < 2; ++mi) {
            const int r = wm * 32 + mi * 16;
            a[mi][0] = __float_as_uint(sA[(r + g) * SSTR + k0 + tg]);
            a[mi][1] = __float_as_uint(sA[(r + g + 8) * SSTR + k0 + tg]);
            a[mi][2] = __float_as_uint(sA[(r + g) * SSTR + k0 + tg + 4]);
            a[mi][3] = __float_as_uint(sA[(r + g + 8) * SSTR + k0 + tg + 4]);
        }
#pragma unroll
        for (int ni = 0; ni < 8; ++ni) {
            const int n = wn * 64 + ni * 8;
            unsigned b0 = __float_as_uint(sB[(n + g) * SSTR + k0 + tg]);
            unsigned b1 = __float_as_uint(sB[(n + g) * SSTR + k0 + tg + 4]);
            mma_tf32(acc[0][ni], a[0], b0, b1);
            mma_tf32(acc[1][ni], a[1], b0, b1);
        }
    }
}

__global__ __launch_bounds__(NTHREADS, 1)
void edge_mlp_kernel(const float* __restrict__ src, const float* __restrict__ dst,
                     const float* __restrict__ edge,
                     const float* __restrict__ W1, const float* __restrict__ W2,
                     const float* __restrict__ b2, float* __restrict__ out) {
    extern __shared__ float smem[];
    float* sA = smem;                 // [128][SSTR]  A chunk / H
    float* sB = smem + BM * SSTR;     // [128][SSTR]  weight chunk, [n][k]

    const int tid = threadIdx.x;
    const int warp = tid >> 5, lane = tid & 31;
    const int wm = warp & 3, wn = warp >> 2;
    const int g = lane >> 2, tg = lane & 3;
    const int e0 = blockIdx.x * BM;

    float acc[2][8][4];
#pragma unroll
    for (int mi = 0; mi < 2; ++mi)
#pragma unroll
        for (int ni = 0; ni < 8; ++ni)
#pragma unroll
            for (int j = 0; j < 4; ++j) acc[mi][ni][j] = 0.f;

    // ---------------- layer 1: three K=128 blocks (src, dest, edge) --------
    const float* Ap = src;
    for (int part = 0; part < 3; ++part) {
        if (part == 1) Ap = dst;
        if (part == 2) Ap = edge;
        __syncthreads();
        // stage A chunk (float4 gmem, tf32 convert into smem)
#pragma unroll
        for (int it = 0; it < 16; ++it) {
            int i = it * NTHREADS + tid;
            int row = i >> 5, c4 = (i & 31) << 2;
            const float4 v = *reinterpret_cast<const float4*>(
                Ap + (size_t)(e0 + row) * DIM + c4);
            float2* d = reinterpret_cast<float2*>(sA + row * SSTR + c4);
            d[0] = make_float2(to_tf32(v.x), to_tf32(v.y));
            d[1] = make_float2(to_tf32(v.z), to_tf32(v.w));
        }
        // stage W1 block, transposed to [n][k]
        const float* Bp = W1 + part * DIM * DIM;
#pragma unroll
        for (int it = 0; it < 16; ++it) {
            int i4 = (it * NTHREADS + tid) << 2;
            float4 v = *reinterpret_cast<const float4*>(Bp + i4);
            int k = i4 >> 7, n = i4 & (DIM - 1);
            sB[(n + 0) * SSTR + k] = to_tf32(v.x);
            sB[(n + 1) * SSTR + k] = to_tf32(v.y);
            sB[(n + 2) * SSTR + k] = to_tf32(v.z);
            sB[(n + 3) * SSTR + k] = to_tf32(v.w);
        }
        __syncthreads();
        mma_block(sA, sB, acc, wm, wn, g, tg);
    }

    __syncthreads();   // all warps done reading sA/sB of last chunk

    // ------------- epilogue 1: + UB[batch] gather, relu, H -> sA (tf32) ----
#pragma unroll
    for (int mi = 0; mi < 2; ++mi) {
        const int rA = wm * 32 + mi * 16 + g;
        const int rB = rA + 8;
        const int ga = g_batch[e0 + rA];
        const int gb = g_batch[e0 + rB];
#pragma unroll
        for (int ni = 0; ni < 8; ++ni) {
            const int c = wn * 64 + ni * 8 + tg * 2;
            float2 ua = *reinterpret_cast<const float2*>(g_UB + ga * DIM + c);
            float2 ub = *reinterpret_cast<const float2*>(g_UB + gb * DIM + c);
            float h0 = fmaxf(acc[mi][ni][0] + ua.x, 0.f);
            float h1 = fmaxf(acc[mi][ni][1] + ua.y, 0.f);
            float h2 = fmaxf(acc[mi][ni][2] + ub.x, 0.f);
            float h3 = fmaxf(acc[mi][ni][3] + ub.y, 0.f);
            *reinterpret_cast<float2*>(sA + rA * SSTR + c) =
                make_float2(to_tf32(h0), to_tf32(h1));
            *reinterpret_cast<float2*>(sA + rB * SSTR + c) =
                make_float2(to_tf32(h2), to_tf32(h3));
        }
    }
    // stage W2 (transposed [n][k])
#pragma unroll
    for (int it = 0; it < 16; ++it) {
        int i4 = (it * NTHREADS + tid) << 2;
        float4 v = *reinterpret_cast<const float4*>(W2 + i4);
        int k = i4 >> 7, n = i4 & (DIM - 1);
        sB[(n + 0) * SSTR + k] = to_tf32(v.x);
        sB[(n + 1) * SSTR + k] = to_tf32(v.y);
        sB[(n + 2) * SSTR + k] = to_tf32(v.z);
        sB[(n + 3) * SSTR + k] = to_tf32(v.w);
    }
    __syncthreads();

    // ---------------- layer 2: out = H @ W2 --------------------------------
#pragma unroll
    for (int mi = 0; mi < 2; ++mi)
#pragma unroll
        for (int ni = 0; ni < 8; ++ni)
#pragma unroll
            for (int j = 0; j < 4; ++j) acc[mi][ni][j] = 0.f;
    mma_block(sA, sB, acc, wm, wn, g, tg);

    // ---------------- epilogue 2: + b2, fp32 store -------------------------
#pragma unroll
    for (int mi = 0; mi < 2; ++mi) {
        const int rA = wm * 32 + mi * 16 + g;
        const int rB = rA + 8;
#pragma unroll
        for (int ni = 0; ni < 8; ++ni) {
            const int c = wn * 64 + ni * 8 + tg * 2;
            float2 bv = *reinterpret_cast<const float2*>(b2 + c);
            *reinterpret_cast<float2*>(out + (size_t)(e0 + rA) * DIM + c) =
                make_float2(acc[mi][ni][0] + bv.x, acc[mi][ni][1] + bv.y);
            *reinterpret_cast<float2*>(out + (size_t)(e0 + rB) * DIM + c) =
                make_float2(acc[mi][ni][2] + bv.x, acc[mi][ni][3] + bv.y);
        }
    }
}

extern "C" void kernel_launch(void* const* d_in, const int* in_sizes, int n_in,
                              void* d_out, int out_size) {
    const float* src  = (const float*)d_in[0];
    const float* dst  = (const float*)d_in[1];
    const float* edge = (const float*)d_in[2];
    const float* u    = (const float*)d_in[3];
    const int*   bat  = (const int*)d_in[4];   // int32 or int64; normalized on device
    const float* W1   = (const float*)d_in[5];
    const float* b1   = (const float*)d_in[6];
    const float* W2   = (const float*)d_in[7];
    const float* b2   = (const float*)d_in[8];
    float* out = (float*)d_out;
    (void)in_sizes; (void)n_in; (void)out_size;

    cudaFuncSetAttribute(edge_mlp_kernel,
                         cudaFuncAttributeMaxDynamicSharedMemorySize, SMEM_BYTES);

    batch_norm_kernel<<<(E_TOTAL + 255) / 256, 256>>>(bat);
    ub_kernel<<<G_TOTAL, DIM>>>(u, W1, b1);
    edge_mlp_kernel<<<E_TOTAL / BM, NTHREADS, SMEM_BYTES>>>(
        src, dst, edge, W1, W2, b2, out);
}

// round 2
// speedup vs baseline: 1.9241x; 1.9241x over previous
#include <cuda_runtime.h>
#include <cstdint>
#include <cstddef>

#define E_TOTAL 400000
#define DIM 128
#define G_TOTAL 512
#define BM 128
#define SSTR 132          // 128 + 4 padding: conflict-free MMA operand LDS
#define NTHREADS 256
#define SMEM_BYTES (2 * BM * SSTR * 4)
#define WCHUNK (DIM * SSTR)            // floats per weight chunk in g_Wt

// Scratch (static device arrays are allowed; allocation is not)
__device__ float g_UB[G_TOTAL * DIM];                    // u @ W1[384:512] + b1 (fp32 exact)
__device__ __align__(16) float g_Wt[4 * WCHUNK];         // tf32 weights, [chunk][n][k] SSTR-padded
__device__ int   g_batch[E_TOTAL];                       // normalized batch indices

__device__ __forceinline__ float to_tf32(float x) {
    unsigned r;
    asm("cvt.rna.tf32.f32 %0, %1;" : "=r"(r) : "f"(x));
    return __uint_as_float(r);
}

__device__ __forceinline__ void cp_async16(uint32_t dst_smem, const void* src) {
    asm volatile("cp.async.cg.shared.global [%0], [%1], 16;\n" :: "r"(dst_smem), "l"(src));
}
__device__ __forceinline__ void cp_async_commit() {
    asm volatile("cp.async.commit_group;\n" ::: "memory");
}
__device__ __forceinline__ void cp_async_wait0() {
    asm volatile("cp.async.wait_group 0;\n" ::: "memory");
}

__device__ __forceinline__ void mma_tf32(float* c, const unsigned* a, unsigned b0, unsigned b1) {
    asm volatile(
        "mma.sync.aligned.m16n8k8.row.col.f32.tf32.tf32.f32 "
        "{%0,%1,%2,%3},{%4,%5,%6,%7},{%8,%9},{%0,%1,%2,%3};\n"
        : "+f"(c[0]), "+f"(c[1]), "+f"(c[2]), "+f"(c[3])
        : "r"(a[0]), "r"(a[1]), "r"(a[2]), "r"(a[3]), "r"(b0), "r"(b1));
}

// ---------------------------------------------------------------------------
// batch may arrive as int32 (JAX x64 disabled) or int64. batch is sorted over
// 400k draws from [0,512); if int64, the high word of the last element is 0;
// if int32, that word is the last (largest) element, nonzero w.h.p.
// ---------------------------------------------------------------------------
__global__ void batch_norm_kernel(const int* __restrict__ bp32) {
    bool is64 = (bp32[E_TOTAL - 1] == 0);
    int i = blockIdx.x * blockDim.x + threadIdx.x;
    if (i < E_TOTAL) {
        g_batch[i] = is64 ? (int)(((const long long*)bp32)[i]) : bp32[i];
    }
}

// UB[g][n] = b1[n] + sum_k u[g][k] * W1[384+k][n]   (exact fp32, tiny)
__global__ void ub_kernel(const float* __restrict__ u, const float* __restrict__ W1,
                          const float* __restrict__ b1) {
    __shared__ float us[DIM];
    int gi = blockIdx.x, n = threadIdx.x;
    us[n] = u[gi * DIM + n];
    __syncthreads();
    float acc = b1[n];
    const float* w = W1 + 3 * DIM * DIM + n;
#pragma unroll 8
    for (int k = 0; k < DIM; ++k) acc += us[k] * w[k * DIM];
    g_UB[gi * DIM + n] = acc;
}

// One-time weight transform: g_Wt[p][n][k] = tf32(W[p][k][n]).
// p 0..2 -> W1 chunks, p=3 -> W2. Pad words (k=128..131) stay zero (bss).
__global__ void wconv_kernel(const float* __restrict__ W1, const float* __restrict__ W2) {
    int p = blockIdx.x, n = blockIdx.y, k = threadIdx.x;
    float v = (p < 3) ? W1[(p * DIM + k) * DIM + n] : W2[k * DIM + n];
    g_Wt[(p * DIM + n) * SSTR + k] = to_tf32(v);
}

// 16 k-steps of m16n8k8 over a 128-deep K chunk.
__device__ __forceinline__ void mma_block(const float* __restrict__ sA,
                                          const float* __restrict__ sB,
                                          float acc[2][8][4],
                                          int wm, int wn, int g, int tg) {
#pragma unroll
    for (int ks = 0; ks < 16; ++ks) {
        const int k0 = ks * 8;
        unsigned a[2][4];
#pragma unroll
        for (int mi = 0; mi < 2; ++mi) {
            const int r = wm * 32 + mi * 16;
            a[mi][0] = __float_as_uint(sA[(r + g) * SSTR + k0 + tg]);
            a[mi][1] = __float_as_uint(sA[(r + g + 8) * SSTR + k0 + tg]);
            a[mi][2] = __float_as_uint(sA[(r + g) * SSTR + k0 + tg + 4]);
            a[mi][3] = __float_as_uint(sA[(r + g + 8) * SSTR + k0 + tg + 4]);
        }
#pragma unroll
        for (int ni = 0; ni < 8; ++ni) {
            const int n = wn * 64 + ni * 8;
            unsigned b0 = __float_as_uint(sB[(n + g) * SSTR + k0 + tg]);
            unsigned b1 = __float_as_uint(sB[(n + g) * SSTR + k0 + tg + 4]);
            mma_tf32(acc[0][ni], a[0], b0, b1);
            mma_tf32(acc[1][ni], a[1], b0, b1);
        }
    }
}

// Load one 128x128 A chunk into registers (16 float4 / thread).
__device__ __forceinline__ void ldg_chunk(const float* __restrict__ Ap, int e0, int tid,
                                          float4 pf[16]) {
#pragma unroll
    for (int it = 0; it < 16; ++it) {
        int i = it * NTHREADS + tid;
        int row = i >> 5, c4 = (i & 31) << 2;
        pf[it] = *reinterpret_cast<const float4*>(Ap + (size_t)(e0 + row) * DIM + c4);
    }
}

// Convert + store registers into sA.
__device__ __forceinline__ void sts_chunk(float* __restrict__ sA, int tid,
                                          const float4 pf[16]) {
#pragma unroll
    for (int it = 0; it < 16; ++it) {
        int i = it * NTHREADS + tid;
        int row = i >> 5, c4 = (i & 31) << 2;
        float2* d = reinterpret_cast<float2*>(sA + row * SSTR + c4);
        d[0] = make_float2(to_tf32(pf[it].x), to_tf32(pf[it].y));
        d[1] = make_float2(to_tf32(pf[it].z), to_tf32(pf[it].w));
    }
}

__global__ __launch_bounds__(NTHREADS, 1)
void edge_mlp_kernel(const float* __restrict__ src, const float* __restrict__ dst,
                     const float* __restrict__ edge,
                     const float* __restrict__ b2, float* __restrict__ out) {
    extern __shared__ float smem[];
    float* sA = smem;                 // [128][SSTR]  A chunk / H
    float* sB = smem + BM * SSTR;     // [128][SSTR]  weight chunk, [n][k]
    const uint32_t sB_u32 = (uint32_t)__cvta_generic_to_shared(sB);

    const int tid = threadIdx.x;
    const int warp = tid >> 5, lane = tid & 31;
    const int wm = warp & 3, wn = warp >> 2;
    const int g = lane >> 2, tg = lane & 3;
    const int e0 = blockIdx.x * BM;

    float acc[2][8][4];
#pragma unroll
    for (int mi = 0; mi < 2; ++mi)
#pragma unroll
        for (int ni = 0; ni < 8; ++ni)
#pragma unroll
            for (int j = 0; j < 4; ++j) acc[mi][ni][j] = 0.f;

    const float* parts[3] = {src, dst, edge};
    float4 pf[16];
    ldg_chunk(parts[0], e0, tid, pf);          // prefetch chunk 0

    // ---------------- layer 1: three K=128 blocks (src, dest, edge) --------
#pragma unroll 1
    for (int part = 0; part < 3; ++part) {
        __syncthreads();                       // prior sA/sB consumers done
        // weight chunk -> sB via conflict-free linear cp.async (pre-transposed tf32)
        {
            const float* wsrc = g_Wt + part * WCHUNK;
#pragma unroll
            for (int it = 0; it < 17; ++it) {
                int i = it * NTHREADS + tid;   // float4 index
                if (i < WCHUNK / 4)
                    cp_async16(sB_u32 + i * 16, wsrc + i * 4);
            }
            cp_async_commit();
        }
        sts_chunk(sA, tid, pf);                // convert + store current A chunk
        if (part < 2) ldg_chunk(parts[part + 1], e0, tid, pf);  // overlap next LDGs with MMA
        cp_async_wait0();
        __syncthreads();
        mma_block(sA, sB, acc, wm, wn, g, tg);
    }

    __syncthreads();                           // all warps done reading sA/sB

    // kick W2 staging early; overlaps with epilogue 1
    {
        const float* wsrc = g_Wt + 3 * WCHUNK;
#pragma unroll
        for (int it = 0; it < 17; ++it) {
            int i = it * NTHREADS + tid;
            if (i < WCHUNK / 4)
                cp_async16(sB_u32 + i * 16, wsrc + i * 4);
        }
        cp_async_commit();
    }

    // ------------- epilogue 1: + UB[batch] gather, relu, H -> sA (tf32) ----
#pragma unroll
    for (int mi = 0; mi < 2; ++mi) {
        const int rA = wm * 32 + mi * 16 + g;
        const int rB = rA + 8;
        const int ga = g_batch[e0 + rA];
        const int gb = g_batch[e0 + rB];
#pragma unroll
        for (int ni = 0; ni < 8; ++ni) {
            const int c = wn * 64 + ni * 8 + tg * 2;
            float2 ua = *reinterpret_cast<const float2*>(g_UB + ga * DIM + c);
            float2 ub = *reinterpret_cast<const float2*>(g_UB + gb * DIM + c);
            float h0 = fmaxf(acc[mi][ni][0] + ua.x, 0.f);
            float h1 = fmaxf(acc[mi][ni][1] + ua.y, 0.f);
            float h2 = fmaxf(acc[mi][ni][2] + ub.x, 0.f);
            float h3 = fmaxf(acc[mi][ni][3] + ub.y, 0.f);
            *reinterpret_cast<float2*>(sA + rA * SSTR + c) =
                make_float2(to_tf32(h0), to_tf32(h1));
            *reinterpret_cast<float2*>(sA + rB * SSTR + c) =
                make_float2(to_tf32(h2), to_tf32(h3));
        }
    }
    cp_async_wait0();
    __syncthreads();

    // ---------------- layer 2: out = H @ W2 --------------------------------
#pragma unroll
    for (int mi = 0; mi < 2; ++mi)
#pragma unroll
        for (int ni = 0; ni < 8; ++ni)
#pragma unroll
            for (int j = 0; j < 4; ++j) acc[mi][ni][j] = 0.f;
    mma_block(sA, sB, acc, wm, wn, g, tg);

    // ---------------- epilogue 2: + b2, fp32 store -------------------------
#pragma unroll
    for (int mi = 0; mi < 2; ++mi) {
        const int rA = wm * 32 + mi * 16 + g;
        const int rB = rA + 8;
#pragma unroll
        for (int ni = 0; ni < 8; ++ni) {
            const int c = wn * 64 + ni * 8 + tg * 2;
            float2 bv = *reinterpret_cast<const float2*>(b2 + c);
            *reinterpret_cast<float2*>(out + (size_t)(e0 + rA) * DIM + c) =
                make_float2(acc[mi][ni][0] + bv.x, acc[mi][ni][1] + bv.y);
            *reinterpret_cast<float2*>(out + (size_t)(e0 + rB) * DIM + c) =
                make_float2(acc[mi][ni][2] + bv.x, acc[mi][ni][3] + bv.y);
        }
    }
}

extern "C" void kernel_launch(void* const* d_in, const int* in_sizes, int n_in,
                              void* d_out, int out_size) {
    const float* src  = (const float*)d_in[0];
    const float* dst  = (const float*)d_in[1];
    const float* edge = (const float*)d_in[2];
    const float* u    = (const float*)d_in[3];
    const int*   bat  = (const int*)d_in[4];
    const float* W1   = (const float*)d_in[5];
    const float* b1   = (const float*)d_in[6];
    const float* W2   = (const float*)d_in[7];
    const float* b2   = (const float*)d_in[8];
    float* out = (float*)d_out;
    (void)in_sizes; (void)n_in; (void)out_size;

    cudaFuncSetAttribute(edge_mlp_kernel,
                         cudaFuncAttributeMaxDynamicSharedMemorySize, SMEM_BYTES);

    batch_norm_kernel<<<(E_TOTAL + 255) / 256, 256>>>(bat);
    ub_kernel<<<G_TOTAL, DIM>>>(u, W1, b1);
    wconv_kernel<<<dim3(4, DIM), DIM>>>(W1, W2);
    edge_mlp_kernel<<<E_TOTAL / BM, NTHREADS, SMEM_BYTES>>>(
        src, dst, edge, b2, out);
}